// round 3
// baseline (speedup 1.0000x reference)
#include <cuda_runtime.h>

#define N_NODES 100000
#define N_EDGES 3200000
#define SCAN_B  1024
#define NB_SCAN ((N_NODES + SCAN_B - 1) / SCAN_B)   // 98

// ---- persistent device scratch (no allocations allowed) ----
__device__ int   g_is64;
__device__ int   g_src32[N_EDGES];
__device__ int   g_dst32[N_EDGES];
__device__ int   g_deg[N_NODES];
__device__ float g_dinv[N_NODES];
__device__ int   g_rowptr[N_NODES + 1];
__device__ int   g_cursor[N_NODES];
__device__ int   g_csrc[N_EDGES];
__device__ int   g_blk[NB_SCAN];
__device__ float g_bufA[(size_t)N_NODES * 32];
__device__ float g_bufB[(size_t)N_NODES * 32];

// ---- dtype detection: int64 edge indices < 2^31 have all-zero high words ----
__global__ void k_detect(const int* __restrict__ ei32) {
    __shared__ int nonzero;
    if (threadIdx.x == 0) nonzero = 0;
    __syncthreads();
    // sample odd int32 words within the first 6.4M words (safe for both dtypes)
    for (int k = threadIdx.x; k < 2048; k += blockDim.x) {
        int pos = 2 * (k * 1000) + 1;              // max 4094001 < 6400000
        if (ei32[pos] != 0) nonzero = 1;
    }
    __syncthreads();
    if (threadIdx.x == 0) g_is64 = nonzero ? 0 : 1;
}

// ---- normalize edge index to int32 src/dst (clamped for safety) ----
__global__ void k_convert(const void* __restrict__ ei) {
    int e = blockIdx.x * blockDim.x + threadIdx.x;
    if (e >= N_EDGES) return;
    int s, d;
    if (g_is64) {
        const long long* p = (const long long*)ei;
        s = (int)p[e]; d = (int)p[N_EDGES + e];
    } else {
        const int* p = (const int*)ei;
        s = p[e]; d = p[N_EDGES + e];
    }
    s = min(max(s, 0), N_NODES - 1);
    d = min(max(d, 0), N_NODES - 1);
    g_src32[e] = s;
    g_dst32[e] = d;
}

// ---- degree / normalization ----
__global__ void k_zero() {
    int i = blockIdx.x * blockDim.x + threadIdx.x;
    if (i < N_NODES) g_deg[i] = 0;
}

__global__ void k_hist() {
    int e = blockIdx.x * blockDim.x + threadIdx.x;
    if (e < N_EDGES) atomicAdd(&g_deg[g_dst32[e]], 1);
}

__global__ void k_dinv() {
    int i = blockIdx.x * blockDim.x + threadIdx.x;
    if (i < N_NODES) g_dinv[i] = rsqrtf((float)(g_deg[i] + 1));  // +1 self-loop
}

// ---- CSR build: 3-phase exclusive scan of in-degrees, then scatter ----
__global__ void k_scan1() {
    __shared__ int s[SCAN_B];
    int tid = threadIdx.x;
    int i = blockIdx.x * SCAN_B + tid;
    int v = (i < N_NODES) ? g_deg[i] : 0;
    s[tid] = v;
    for (int off = 1; off < SCAN_B; off <<= 1) {
        __syncthreads();
        int t = (tid >= off) ? s[tid - off] : 0;
        __syncthreads();
        s[tid] += t;
    }
    __syncthreads();
    if (i < N_NODES) g_rowptr[i] = s[tid] - v;           // local exclusive
    if (tid == SCAN_B - 1) g_blk[blockIdx.x] = s[tid];   // block total
}

__global__ void k_scan2() {
    int run = 0;
    for (int b = 0; b < NB_SCAN; b++) { int t = g_blk[b]; g_blk[b] = run; run += t; }
}

__global__ void k_scan3() {
    int i = blockIdx.x * blockDim.x + threadIdx.x;
    if (i < N_NODES) {
        int r = g_rowptr[i] + g_blk[i / SCAN_B];
        g_rowptr[i] = r;
        g_cursor[i] = r;
    }
    if (i == 0) g_rowptr[N_NODES] = N_EDGES;
}

__global__ void k_scatter() {
    int e = blockIdx.x * blockDim.x + threadIdx.x;
    if (e < N_EDGES) {
        int p = atomicAdd(&g_cursor[g_dst32[e]], 1);
        g_csrc[p] = g_src32[e];
    }
}

// ---- dense: g[node][c] = (sum_k x[node][k] * W[k][c]) * dinv[node] ----
template <int IN, int OUT>
__global__ void k_gemm(const float* __restrict__ x, const float* __restrict__ W,
                       float* __restrict__ g) {
    __shared__ float Ws[IN * OUT];
    for (int i = threadIdx.x; i < IN * OUT; i += blockDim.x) Ws[i] = W[i];
    __syncthreads();
    int gid = blockIdx.x * blockDim.x + threadIdx.x;
    int node = gid / OUT, c = gid % OUT;
    if (node >= N_NODES) return;
    const float* xr = x + (size_t)node * IN;
    float acc = 0.f;
#pragma unroll
    for (int k = 0; k < IN; k++) acc += xr[k] * Ws[k * OUT + c];
    g[(size_t)node * OUT + c] = acc * g_dinv[node];
}

// ---- aggregate: out[i] = f( dinv[i] * (sum_{e in CSR[i]} g[src] + g[i]) + b ) ----
// one warp per node; lanes split into 32/D edge groups, shuffle-reduce at the end
template <int D, bool RELU>
__global__ void k_agg(const float* __restrict__ g, const float* __restrict__ bias,
                      float* __restrict__ out) {
    int node = (int)((blockIdx.x * blockDim.x + threadIdx.x) >> 5);
    int lane = threadIdx.x & 31;
    if (node >= N_NODES) return;
    constexpr int G = 32 / D;
    int grp = lane / D, ch = lane % D;
    int s = g_rowptr[node], e = g_rowptr[node + 1];
    float acc = 0.f;
    for (int i = s + grp; i < e; i += G) {
        int src = g_csrc[i];
        acc += g[(size_t)src * D + ch];
    }
#pragma unroll
    for (int off = 16; off >= D; off >>= 1)
        acc += __shfl_xor_sync(0xffffffffu, acc, off);
    acc += g[(size_t)node * D + ch];                    // self-loop (g already * dinv)
    float r = acc * g_dinv[node] + bias[ch];
    if (RELU) r = fmaxf(r, 0.f);
    if (lane < D) out[(size_t)node * D + ch] = r;
}

extern "C" void kernel_launch(void* const* d_in, const int* in_sizes, int n_in,
                              void* d_out, int out_size) {
    const float* x  = (const float*)d_in[0];
    const void*  ei = d_in[1];
    const float* W1 = (const float*)d_in[2];
    const float* b1 = (const float*)d_in[3];
    const float* W2 = (const float*)d_in[4];
    const float* b2 = (const float*)d_in[5];
    const float* W3 = (const float*)d_in[6];
    const float* b3 = (const float*)d_in[7];
    float* out = (float*)d_out;

    float *bufA = nullptr, *bufB = nullptr;
    cudaGetSymbolAddress((void**)&bufA, g_bufA);
    cudaGetSymbolAddress((void**)&bufB, g_bufB);

    const int TB = 256;
    const int nbN = (N_NODES + TB - 1) / TB;
    const int nbE = (N_EDGES + TB - 1) / TB;
    const int nbW = (N_NODES * 32 + TB - 1) / TB;   // warp-per-node kernels

    // dtype detection + index normalization
    k_detect <<<1, 256>>>((const int*)ei);
    k_convert<<<nbE, TB>>>(ei);

    // normalization + CSR build (recomputed every launch: deterministic work)
    k_zero   <<<nbN, TB>>>();
    k_hist   <<<nbE, TB>>>();
    k_dinv   <<<nbN, TB>>>();
    k_scan1  <<<NB_SCAN, SCAN_B>>>();
    k_scan2  <<<1, 1>>>();
    k_scan3  <<<nbN, TB>>>();
    k_scatter<<<nbE, TB>>>();

    // layer 1: 128 -> 32, relu
    k_gemm<128, 32><<<(N_NODES * 32 + TB - 1) / TB, TB>>>(x, W1, bufA);
    k_agg<32, true><<<nbW, TB>>>(bufA, b1, bufB);
    // layer 2: 32 -> 16, relu
    k_gemm<32, 16><<<(N_NODES * 16 + TB - 1) / TB, TB>>>(bufB, W2, bufA);
    k_agg<16, true><<<nbW, TB>>>(bufA, b2, bufB);
    // layer 3: 16 -> 8, no relu
    k_gemm<16, 8><<<(N_NODES * 8 + TB - 1) / TB, TB>>>(bufB, W3, bufA);
    k_agg<8, false><<<nbW, TB>>>(bufA, b3, out);
}

// round 4
// speedup vs baseline: 1.3088x; 1.3088x over previous
#include <cuda_runtime.h>

#define N_NODES 100000
#define N_EDGES 3200000
#define SCAN_B  1024
#define NB_SCAN ((N_NODES + SCAN_B - 1) / SCAN_B)   // 98

// ---- persistent device scratch (no allocations allowed) ----
__device__ int   g_is64;
__device__ int   g_src32[N_EDGES];
__device__ int   g_dst32[N_EDGES];
__device__ int   g_deg[N_NODES];
__device__ float g_dinv[N_NODES];
__device__ int   g_rowptr[N_NODES + 1];
__device__ int   g_cursor[N_NODES];
__device__ int   g_csrc[N_EDGES];
__device__ int   g_blk[NB_SCAN];
__device__ float g_bufA[(size_t)N_NODES * 32];
__device__ float g_bufB[(size_t)N_NODES * 32];

// ---- dtype detection: int64 edge indices < 2^31 have all-zero high words ----
__global__ void k_detect(const int* __restrict__ ei32) {
    __shared__ int nonzero;
    if (threadIdx.x == 0) nonzero = 0;
    __syncthreads();
    for (int k = threadIdx.x; k < 2048; k += blockDim.x) {
        int pos = 2 * (k * 1000) + 1;              // max 4094001 < 6400000
        if (ei32[pos] != 0) nonzero = 1;
    }
    __syncthreads();
    if (threadIdx.x == 0) g_is64 = nonzero ? 0 : 1;
}

// ---- normalize to int32 src/dst (clamped) + fused in-degree histogram ----
__global__ void k_convert_hist(const void* __restrict__ ei) {
    int e = blockIdx.x * blockDim.x + threadIdx.x;
    if (e >= N_EDGES) return;
    int s, d;
    if (g_is64) {
        const long long* p = (const long long*)ei;
        s = (int)p[e]; d = (int)p[N_EDGES + e];
    } else {
        const int* p = (const int*)ei;
        s = p[e]; d = p[N_EDGES + e];
    }
    s = min(max(s, 0), N_NODES - 1);
    d = min(max(d, 0), N_NODES - 1);
    g_src32[e] = s;
    g_dst32[e] = d;
    atomicAdd(&g_deg[d], 1);
}

// ---- CSR build: scan of in-degrees (dinv fused in phase 1), then scatter ----
__global__ void k_scan1() {
    __shared__ int s[SCAN_B];
    int tid = threadIdx.x;
    int i = blockIdx.x * SCAN_B + tid;
    int v = (i < N_NODES) ? g_deg[i] : 0;
    if (i < N_NODES) g_dinv[i] = rsqrtf((float)(v + 1));  // +1 self-loop
    s[tid] = v;
    for (int off = 1; off < SCAN_B; off <<= 1) {
        __syncthreads();
        int t = (tid >= off) ? s[tid - off] : 0;
        __syncthreads();
        s[tid] += t;
    }
    __syncthreads();
    if (i < N_NODES) g_rowptr[i] = s[tid] - v;           // local exclusive
    if (tid == SCAN_B - 1) g_blk[blockIdx.x] = s[tid];   // block total
}

__global__ void k_scan2() {                               // parallel 128-wide scan
    __shared__ int s[128];
    int tid = threadIdx.x;
    int v = (tid < NB_SCAN) ? g_blk[tid] : 0;
    s[tid] = v;
    for (int off = 1; off < 128; off <<= 1) {
        __syncthreads();
        int t = (tid >= off) ? s[tid - off] : 0;
        __syncthreads();
        s[tid] += t;
    }
    __syncthreads();
    if (tid < NB_SCAN) g_blk[tid] = s[tid] - v;           // exclusive
}

__global__ void k_scan3() {
    int i = blockIdx.x * blockDim.x + threadIdx.x;
    if (i < N_NODES) {
        int r = g_rowptr[i] + g_blk[i / SCAN_B];
        g_rowptr[i] = r;
        g_cursor[i] = r;
    }
    if (i == 0) g_rowptr[N_NODES] = N_EDGES;
}

__global__ void k_scatter() {
    int e = blockIdx.x * blockDim.x + threadIdx.x;
    if (e < N_EDGES) {
        int p = atomicAdd(&g_cursor[g_dst32[e]], 1);
        g_csrc[p] = g_src32[e];
    }
}

// ---- layer-1 GEMM: 128 -> 32, register-tiled (4 nodes/thread) ----
// 3125 blocks x 256 threads; block covers 32 nodes (exact: 100000 = 3125*32)
__global__ void k_gemm1(const float* __restrict__ x, const float* __restrict__ W,
                        float* __restrict__ g) {
    __shared__ float Xs[32 * 128];
    __shared__ float Ws[128 * 32];
    int tid = threadIdx.x;
    int nb = blockIdx.x * 32;

    const float4* W4 = (const float4*)W;
    float4* Ws4 = (float4*)Ws;
    for (int i = tid; i < 1024; i += 256) Ws4[i] = W4[i];
    const float4* X4 = (const float4*)(x + (size_t)nb * 128);
    float4* Xs4 = (float4*)Xs;
    for (int i = tid; i < 1024; i += 256) Xs4[i] = X4[i];
    __syncthreads();

    int w = tid >> 5, c = tid & 31;
    const float* x0 = Xs + (w * 4 + 0) * 128;
    const float* x1 = Xs + (w * 4 + 1) * 128;
    const float* x2 = Xs + (w * 4 + 2) * 128;
    const float* x3 = Xs + (w * 4 + 3) * 128;
    float a0 = 0.f, a1 = 0.f, a2 = 0.f, a3 = 0.f;
#pragma unroll 8
    for (int k = 0; k < 128; k++) {
        float wv = Ws[k * 32 + c];
        a0 += x0[k] * wv; a1 += x1[k] * wv;
        a2 += x2[k] * wv; a3 += x3[k] * wv;
    }
    int n0 = nb + w * 4;
    g[(size_t)(n0 + 0) * 32 + c] = a0 * g_dinv[n0 + 0];
    g[(size_t)(n0 + 1) * 32 + c] = a1 * g_dinv[n0 + 1];
    g[(size_t)(n0 + 2) * 32 + c] = a2 * g_dinv[n0 + 2];
    g[(size_t)(n0 + 3) * 32 + c] = a3 * g_dinv[n0 + 3];
}

// ---- small GEMMs (layers 2,3): g[node][c] = (x[node] . W[:,c]) * dinv ----
template <int IN, int OUT>
__global__ void k_gemm(const float* __restrict__ x, const float* __restrict__ W,
                       float* __restrict__ g) {
    __shared__ float Ws[IN * OUT];
    for (int i = threadIdx.x; i < IN * OUT; i += blockDim.x) Ws[i] = W[i];
    __syncthreads();
    int gid = blockIdx.x * blockDim.x + threadIdx.x;
    int node = gid / OUT, c = gid % OUT;
    if (node >= N_NODES) return;
    const float4* xr = (const float4*)(x + (size_t)node * IN);
    float acc = 0.f;
#pragma unroll
    for (int k4 = 0; k4 < IN / 4; k4++) {
        float4 v = xr[k4];
        acc += v.x * Ws[(4 * k4 + 0) * OUT + c];
        acc += v.y * Ws[(4 * k4 + 1) * OUT + c];
        acc += v.z * Ws[(4 * k4 + 2) * OUT + c];
        acc += v.w * Ws[(4 * k4 + 3) * OUT + c];
    }
    g[(size_t)node * OUT + c] = acc * g_dinv[node];
}

// ---- aggregate: out[i] = f( dinv[i]*(sum_{e in CSR[i]} g[src] + g[i]) + b ) ----
// one warp per node; 32/D edge groups; 4x unrolled for MLP=4
template <int D, bool RELU>
__global__ void k_agg(const float* __restrict__ g, const float* __restrict__ bias,
                      float* __restrict__ out) {
    int node = (int)((blockIdx.x * blockDim.x + threadIdx.x) >> 5);
    int lane = threadIdx.x & 31;
    if (node >= N_NODES) return;
    constexpr int G = 32 / D;
    int grp = lane / D, ch = lane % D;
    int s = g_rowptr[node], e = g_rowptr[node + 1];
    float a0 = 0.f, a1 = 0.f, a2 = 0.f, a3 = 0.f;
    int i = s + grp;
    for (; i + 3 * G < e; i += 4 * G) {
        int s0 = __ldg(&g_csrc[i]);
        int s1 = __ldg(&g_csrc[i + G]);
        int s2 = __ldg(&g_csrc[i + 2 * G]);
        int s3 = __ldg(&g_csrc[i + 3 * G]);
        a0 += __ldg(&g[(size_t)s0 * D + ch]);
        a1 += __ldg(&g[(size_t)s1 * D + ch]);
        a2 += __ldg(&g[(size_t)s2 * D + ch]);
        a3 += __ldg(&g[(size_t)s3 * D + ch]);
    }
    for (; i < e; i += G) a0 += __ldg(&g[(size_t)g_csrc[i] * D + ch]);
    float acc = (a0 + a1) + (a2 + a3);
#pragma unroll
    for (int off = 16; off >= D; off >>= 1)
        acc += __shfl_xor_sync(0xffffffffu, acc, off);
    acc += g[(size_t)node * D + ch];                     // self-loop (g already * dinv)
    float r = acc * g_dinv[node] + bias[ch];
    if (RELU) r = fmaxf(r, 0.f);
    if (lane < D) out[(size_t)node * D + ch] = r;
}

extern "C" void kernel_launch(void* const* d_in, const int* in_sizes, int n_in,
                              void* d_out, int out_size) {
    const float* x  = (const float*)d_in[0];
    const void*  ei = d_in[1];
    const float* W1 = (const float*)d_in[2];
    const float* b1 = (const float*)d_in[3];
    const float* W2 = (const float*)d_in[4];
    const float* b2 = (const float*)d_in[5];
    const float* W3 = (const float*)d_in[6];
    const float* b3 = (const float*)d_in[7];
    float* out = (float*)d_out;

    float *bufA = nullptr, *bufB = nullptr;
    int* degPtr = nullptr;
    cudaGetSymbolAddress((void**)&bufA, g_bufA);
    cudaGetSymbolAddress((void**)&bufB, g_bufB);
    cudaGetSymbolAddress((void**)&degPtr, g_deg);

    const int TB = 256;
    const int nbN = (N_NODES + TB - 1) / TB;
    const int nbE = (N_EDGES + TB - 1) / TB;
    const int nbW = (N_NODES * 32 + TB - 1) / TB;   // warp-per-node kernels

    cudaMemsetAsync(degPtr, 0, N_NODES * sizeof(int));
    k_detect      <<<1, 256>>>((const int*)ei);
    k_convert_hist<<<nbE, TB>>>(ei);
    k_scan1       <<<NB_SCAN, SCAN_B>>>();
    k_scan2       <<<1, 128>>>();
    k_scan3       <<<nbN, TB>>>();
    k_scatter     <<<nbE, TB>>>();

    // layer 1: 128 -> 32, relu
    k_gemm1<<<N_NODES / 32, 256>>>(x, W1, bufA);
    k_agg<32, true><<<nbW, TB>>>(bufA, b1, bufB);
    // layer 2: 32 -> 16, relu
    k_gemm<32, 16><<<(N_NODES * 16 + TB - 1) / TB, TB>>>(bufB, W2, bufA);
    k_agg<16, true><<<nbW, TB>>>(bufA, b2, bufB);
    // layer 3: 16 -> 8, no relu
    k_gemm<16, 8><<<(N_NODES * 8 + TB - 1) / TB, TB>>>(bufB, W3, bufA);
    k_agg<8, false><<<nbW, TB>>>(bufA, b3, out);
}

// round 5
// speedup vs baseline: 1.3185x; 1.0074x over previous
#include <cuda_runtime.h>

#define N_NODES 100000
#define N_EDGES 3200000
#define SCAN_B  1024
#define NB_SCAN ((N_NODES + SCAN_B - 1) / SCAN_B)   // 98

// ---- persistent device scratch (no allocations allowed) ----
__device__ int   g_is64;
__device__ int2  g_sd[N_EDGES];
__device__ int   g_deg[N_NODES];
__device__ float g_dinv[N_NODES];
__device__ int   g_rowptr[N_NODES + 1];
__device__ int   g_cursor[N_NODES];
__device__ int   g_csrc[N_EDGES];
__device__ int   g_blk[NB_SCAN];
__device__ float g_bufA[(size_t)N_NODES * 32];
__device__ float g_bufB[(size_t)N_NODES * 32];

// ---- dtype detection: int64 edge indices < 2^31 have all-zero high words ----
__global__ void k_detect(const int* __restrict__ ei32) {
    __shared__ int nonzero;
    if (threadIdx.x == 0) nonzero = 0;
    __syncthreads();
    for (int k = threadIdx.x; k < 2048; k += blockDim.x) {
        int pos = 2 * (k * 1000) + 1;              // max 4094001 < 6400000
        if (ei32[pos] != 0) nonzero = 1;
    }
    __syncthreads();
    if (threadIdx.x == 0) g_is64 = nonzero ? 0 : 1;
}

// ---- normalize to packed int32 (src,dst) + fused in-degree histogram ----
__global__ void k_convert_hist(const void* __restrict__ ei) {
    int e = blockIdx.x * blockDim.x + threadIdx.x;
    if (e >= N_EDGES) return;
    int s, d;
    if (g_is64) {
        const long long* p = (const long long*)ei;
        s = (int)p[e]; d = (int)p[N_EDGES + e];
    } else {
        const int* p = (const int*)ei;
        s = p[e]; d = p[N_EDGES + e];
    }
    s = min(max(s, 0), N_NODES - 1);
    d = min(max(d, 0), N_NODES - 1);
    g_sd[e] = make_int2(s, d);
    atomicAdd(&g_deg[d], 1);
}

// ---- CSR build: scan of in-degrees (dinv fused in phase 1), then scatter ----
__global__ void k_scan1() {
    __shared__ int s[SCAN_B];
    int tid = threadIdx.x;
    int i = blockIdx.x * SCAN_B + tid;
    int v = (i < N_NODES) ? g_deg[i] : 0;
    if (i < N_NODES) g_dinv[i] = rsqrtf((float)(v + 1));  // +1 self-loop
    s[tid] = v;
    for (int off = 1; off < SCAN_B; off <<= 1) {
        __syncthreads();
        int t = (tid >= off) ? s[tid - off] : 0;
        __syncthreads();
        s[tid] += t;
    }
    __syncthreads();
    if (i < N_NODES) g_rowptr[i] = s[tid] - v;           // local exclusive
    if (tid == SCAN_B - 1) g_blk[blockIdx.x] = s[tid];   // block total
}

__global__ void k_scan2() {                               // parallel 128-wide scan
    __shared__ int s[128];
    int tid = threadIdx.x;
    int v = (tid < NB_SCAN) ? g_blk[tid] : 0;
    s[tid] = v;
    for (int off = 1; off < 128; off <<= 1) {
        __syncthreads();
        int t = (tid >= off) ? s[tid - off] : 0;
        __syncthreads();
        s[tid] += t;
    }
    __syncthreads();
    if (tid < NB_SCAN) g_blk[tid] = s[tid] - v;           // exclusive
}

__global__ void k_scan3() {
    int i = blockIdx.x * blockDim.x + threadIdx.x;
    if (i < N_NODES) {
        int r = g_rowptr[i] + g_blk[i / SCAN_B];
        g_rowptr[i] = r;
        g_cursor[i] = r;
    }
    if (i == 0) g_rowptr[N_NODES] = N_EDGES;
}

__global__ void k_scatter() {
    int e = blockIdx.x * blockDim.x + threadIdx.x;
    if (e < N_EDGES) {
        int2 sd = g_sd[e];
        int p = atomicAdd(&g_cursor[sd.y], 1);
        g_csrc[p] = sd.x;
    }
}

// ---- layer-1 GEMM: 128 -> 32, register-tiled (4 nodes/thread), * dinv ----
__global__ void k_gemm1(const float* __restrict__ x, const float* __restrict__ W,
                        float* __restrict__ g) {
    __shared__ float Xs[32 * 128];
    __shared__ float Ws[128 * 32];
    int tid = threadIdx.x;
    int nb = blockIdx.x * 32;

    const float4* W4 = (const float4*)W;
    float4* Ws4 = (float4*)Ws;
    for (int i = tid; i < 1024; i += 256) Ws4[i] = W4[i];
    const float4* X4 = (const float4*)(x + (size_t)nb * 128);
    float4* Xs4 = (float4*)Xs;
    for (int i = tid; i < 1024; i += 256) Xs4[i] = X4[i];
    __syncthreads();

    int w = tid >> 5, c = tid & 31;
    const float* x0 = Xs + (w * 4 + 0) * 128;
    const float* x1 = Xs + (w * 4 + 1) * 128;
    const float* x2 = Xs + (w * 4 + 2) * 128;
    const float* x3 = Xs + (w * 4 + 3) * 128;
    float a0 = 0.f, a1 = 0.f, a2 = 0.f, a3 = 0.f;
#pragma unroll 8
    for (int k = 0; k < 128; k++) {
        float wv = Ws[k * 32 + c];
        a0 += x0[k] * wv; a1 += x1[k] * wv;
        a2 += x2[k] * wv; a3 += x3[k] * wv;
    }
    int n0 = nb + w * 4;
    g[(size_t)(n0 + 0) * 32 + c] = a0 * g_dinv[n0 + 0];
    g[(size_t)(n0 + 1) * 32 + c] = a1 * g_dinv[n0 + 1];
    g[(size_t)(n0 + 2) * 32 + c] = a2 * g_dinv[n0 + 2];
    g[(size_t)(n0 + 3) * 32 + c] = a3 * g_dinv[n0 + 3];
}

// ---- agg1 + fused gemm2:  h = relu(dinv*(gather+self)+b1);  g2 = (h@W2)*dinv ----
// one warp per node, D=32 (ch = lane). Output 16 channels.
__global__ void k_agg1_gemm2(const float* __restrict__ g, const float* __restrict__ b1,
                             const float* __restrict__ W2, float* __restrict__ g2) {
    __shared__ float W2s[32 * 16];
    for (int i = threadIdx.x; i < 512; i += blockDim.x) W2s[i] = W2[i];
    __syncthreads();
    int node = (int)((blockIdx.x * blockDim.x + threadIdx.x) >> 5);
    int lane = threadIdx.x & 31;
    if (node >= N_NODES) return;
    int s = g_rowptr[node], e = g_rowptr[node + 1];
    float a0 = 0.f, a1 = 0.f, a2 = 0.f, a3 = 0.f;
    int i = s;
    for (; i + 3 < e; i += 4) {
        int s0 = __ldg(&g_csrc[i]);
        int s1 = __ldg(&g_csrc[i + 1]);
        int s2 = __ldg(&g_csrc[i + 2]);
        int s3 = __ldg(&g_csrc[i + 3]);
        a0 += __ldg(&g[(size_t)s0 * 32 + lane]);
        a1 += __ldg(&g[(size_t)s1 * 32 + lane]);
        a2 += __ldg(&g[(size_t)s2 * 32 + lane]);
        a3 += __ldg(&g[(size_t)s3 * 32 + lane]);
    }
    for (; i < e; i++) a0 += __ldg(&g[(size_t)g_csrc[i] * 32 + lane]);
    float acc = (a0 + a1) + (a2 + a3);
    acc += g[(size_t)node * 32 + lane];                  // self-loop (g already * dinv)
    float dn = g_dinv[node];
    float h = fmaxf(acc * dn + b1[lane], 0.f);

    // fused 32->16 GEMM: low half lanes cover ch 0..15, high half ch 16..31
    float o = 0.f;
    int cp = lane & 15;
    int base = (lane >= 16) ? 16 : 0;
#pragma unroll
    for (int t = 0; t < 16; t++) {
        int ch = t + base;
        float v = __shfl_sync(0xffffffffu, h, ch);
        o += v * W2s[ch * 16 + cp];
    }
    o += __shfl_xor_sync(0xffffffffu, o, 16);
    if (lane < 16) g2[(size_t)node * 16 + lane] = o * dn;
}

// ---- agg2 + fused gemm3:  h = relu(dinv*(gather+self)+b2);  g3 = (h@W3)*dinv ----
// one warp per node, D=16 (2 edge groups). Output 8 channels.
__global__ void k_agg2_gemm3(const float* __restrict__ g, const float* __restrict__ b2,
                             const float* __restrict__ W3, float* __restrict__ g3) {
    __shared__ float W3s[16 * 8];
    for (int i = threadIdx.x; i < 128; i += blockDim.x) W3s[i] = W3[i];
    __syncthreads();
    int node = (int)((blockIdx.x * blockDim.x + threadIdx.x) >> 5);
    int lane = threadIdx.x & 31;
    if (node >= N_NODES) return;
    int grp = lane >> 4, ch = lane & 15;
    int s = g_rowptr[node], e = g_rowptr[node + 1];
    float a0 = 0.f, a1 = 0.f, a2 = 0.f, a3 = 0.f;
    int i = s + grp;
    for (; i + 6 < e; i += 8) {
        int s0 = __ldg(&g_csrc[i]);
        int s1 = __ldg(&g_csrc[i + 2]);
        int s2 = __ldg(&g_csrc[i + 4]);
        int s3 = __ldg(&g_csrc[i + 6]);
        a0 += __ldg(&g[(size_t)s0 * 16 + ch]);
        a1 += __ldg(&g[(size_t)s1 * 16 + ch]);
        a2 += __ldg(&g[(size_t)s2 * 16 + ch]);
        a3 += __ldg(&g[(size_t)s3 * 16 + ch]);
    }
    for (; i < e; i += 2) a0 += __ldg(&g[(size_t)g_csrc[i] * 16 + ch]);
    float acc = (a0 + a1) + (a2 + a3);
    acc += __shfl_xor_sync(0xffffffffu, acc, 16);        // combine two edge groups
    acc += g[(size_t)node * 16 + ch];                    // self-loop
    float dn = g_dinv[node];
    float h = fmaxf(acc * dn + b2[ch], 0.f);             // valid on all lanes (dup halves)

    // fused 16->8 GEMM: low half covers ch 0..7, high half ch 8..15
    float o = 0.f;
    int cp = lane & 7;
    int base = (lane >= 16) ? 8 : 0;
#pragma unroll
    for (int t = 0; t < 8; t++) {
        int c2 = t + base;                               // source lane = its channel
        float v = __shfl_sync(0xffffffffu, h, c2);
        o += v * W3s[c2 * 8 + cp];
    }
    o += __shfl_xor_sync(0xffffffffu, o, 16);
    if (lane < 8) g3[(size_t)node * 8 + lane] = o * dn;
}

// ---- final aggregate, D=8, no relu, bias b3 ----
__global__ void k_agg3(const float* __restrict__ g, const float* __restrict__ bias,
                       float* __restrict__ out) {
    int node = (int)((blockIdx.x * blockDim.x + threadIdx.x) >> 5);
    int lane = threadIdx.x & 31;
    if (node >= N_NODES) return;
    int grp = lane >> 3, ch = lane & 7;
    int s = g_rowptr[node], e = g_rowptr[node + 1];
    float a0 = 0.f, a1 = 0.f, a2 = 0.f, a3 = 0.f;
    int i = s + grp;
    for (; i + 12 < e; i += 16) {
        int s0 = __ldg(&g_csrc[i]);
        int s1 = __ldg(&g_csrc[i + 4]);
        int s2 = __ldg(&g_csrc[i + 8]);
        int s3 = __ldg(&g_csrc[i + 12]);
        a0 += __ldg(&g[(size_t)s0 * 8 + ch]);
        a1 += __ldg(&g[(size_t)s1 * 8 + ch]);
        a2 += __ldg(&g[(size_t)s2 * 8 + ch]);
        a3 += __ldg(&g[(size_t)s3 * 8 + ch]);
    }
    for (; i < e; i += 4) a0 += __ldg(&g[(size_t)g_csrc[i] * 8 + ch]);
    float acc = (a0 + a1) + (a2 + a3);
#pragma unroll
    for (int off = 16; off >= 8; off >>= 1)
        acc += __shfl_xor_sync(0xffffffffu, acc, off);
    acc += g[(size_t)node * 8 + ch];                     // self-loop
    float r = acc * g_dinv[node] + bias[ch];
    if (lane < 8) out[(size_t)node * 8 + ch] = r;
}

extern "C" void kernel_launch(void* const* d_in, const int* in_sizes, int n_in,
                              void* d_out, int out_size) {
    const float* x  = (const float*)d_in[0];
    const void*  ei = d_in[1];
    const float* W1 = (const float*)d_in[2];
    const float* b1 = (const float*)d_in[3];
    const float* W2 = (const float*)d_in[4];
    const float* b2 = (const float*)d_in[5];
    const float* W3 = (const float*)d_in[6];
    const float* b3 = (const float*)d_in[7];
    float* out = (float*)d_out;

    float *bufA = nullptr, *bufB = nullptr;
    int* degPtr = nullptr;
    cudaGetSymbolAddress((void**)&bufA, g_bufA);
    cudaGetSymbolAddress((void**)&bufB, g_bufB);
    cudaGetSymbolAddress((void**)&degPtr, g_deg);

    // one-time stream/event creation (host resources only, no device memory)
    static cudaStream_t s2 = nullptr;
    static cudaEvent_t evA = nullptr, evB = nullptr;
    if (!s2) {
        cudaStreamCreateWithFlags(&s2, cudaStreamNonBlocking);
        cudaEventCreateWithFlags(&evA, cudaEventDisableTiming);
        cudaEventCreateWithFlags(&evB, cudaEventDisableTiming);
    }

    const int TB = 256;
    const int nbN = (N_NODES + TB - 1) / TB;
    const int nbE = (N_EDGES + TB - 1) / TB;
    const int nbW = (N_NODES * 32 + TB - 1) / TB;   // warp-per-node kernels

    cudaMemsetAsync(degPtr, 0, N_NODES * sizeof(int));
    k_detect      <<<1, 256>>>((const int*)ei);
    k_convert_hist<<<nbE, TB>>>(ei);
    k_scan1       <<<NB_SCAN, SCAN_B>>>();
    cudaEventRecord(evA, 0);                        // dinv ready

    // side stream: gemm1 overlaps scan2/scan3/scatter
    cudaStreamWaitEvent(s2, evA, 0);
    k_gemm1<<<N_NODES / 32, 256, 0, s2>>>(x, W1, bufA);
    cudaEventRecord(evB, s2);

    k_scan2       <<<1, 128>>>();
    k_scan3       <<<nbN, TB>>>();
    k_scatter     <<<nbE, TB>>>();
    cudaStreamWaitEvent(0, evB, 0);                 // join gemm1

    k_agg1_gemm2<<<nbW, TB>>>(bufA, b1, W2, bufB);
    k_agg2_gemm3<<<nbW, TB>>>(bufB, b2, W3, bufA);
    k_agg3      <<<nbW, TB>>>(bufA, b3, out);
}